// round 17
// baseline (speedup 1.0000x reference)
#include <cuda_runtime.h>
#include <cuda_bf16.h>
#include <cstdint>
#include <cstddef>

// ---------------------------------------------------------------------------
// Constants (total_steps=1000 -> K=10 bins of S=100)
// ---------------------------------------------------------------------------
#define T_STEPS 1000
#define SBIN    100
#define KBINS   10

#define H0 100
#define W0 368
#define H1 50
#define W1 184
#define H2 25
#define W2 92
#define H3 13
#define W3 46
#define H4 7
#define W4 23

#define P0 (H0*W0)   // 36800
#define P1 (H1*W1)   // 9200
#define P2 (H2*W2)   // 2300
#define P3 (H3*W3)   // 598
#define P4 (H4*W4)   // 161

#define N1 (4*P1)    // 36800
#define N2 (8*P2)    // 18400
#define N3 (16*P3)   // 9568
#define N4 (32*P4)   // 5152

// ---------------------------------------------------------------------------
// Scratch (device globals). Time-indexed data is CHANNEL-LAST:
//   currents c[t][pos][oc], spikes s[t][pos][ic].
// Layer 1 currents are never materialized (fused conv+scan).
// ---------------------------------------------------------------------------
__device__ unsigned char g_s1[(size_t)T_STEPS * N1];
__device__ float         g_c2[(size_t)T_STEPS * N2];
__device__ unsigned char g_s2[(size_t)T_STEPS * N2];
__device__ float         g_c3[(size_t)T_STEPS * N3];
__device__ unsigned char g_s3[(size_t)T_STEPS * N3];
__device__ float         g_c4[(size_t)T_STEPS * N4];

__device__ float g_skip1[80  * P1];
__device__ float g_skip2[160 * P2];
__device__ float g_skip3[320 * P3];
__device__ float g_skip4[640 * P4];

__device__ float g_d4[64 * P4];
__device__ float g_u4[64 * P3];
__device__ float g_d3[32 * P3];
__device__ float g_u3[32 * P2];
__device__ float g_d2[16 * P2];
__device__ float g_u2[16 * P1];
__device__ float g_d1[8  * P1];
__device__ float g_u1[8  * P0];

// Device-side buffer selectors (compile-time)
template<int L> __device__ __forceinline__ float* cbuf_of() {
    if constexpr (L == 2) return g_c2;
    else if constexpr (L == 3) return g_c3;
    else return g_c4;
}
template<int L> __device__ __forceinline__ unsigned char* sbuf_of() {
    if constexpr (L == 1) return g_s1;
    else if constexpr (L == 2) return g_s2;
    else return g_s3;
}
template<int L> __device__ __forceinline__ float* skip_of() {
    if constexpr (L == 2) return g_skip2;
    else if constexpr (L == 3) return g_skip3;
    else return g_skip4;
}

// ---------------------------------------------------------------------------
// FUSED layer 1 (tile-parallel): conv(stride2, SAME) + membrane scan.
// Block = 16 output cols x 4 oc (64 threads, 2 warps -> cheap barrier).
// Grid (12, 50) = 600 blocks -> ~4 blocks/SM of independent per-step chains.
// Depth-8 cp.async smem ring; load coordinates hoisted out of the time loop.
// ---------------------------------------------------------------------------
#define L1_D    8
#define L1_TILE 99    // 3 rows x 33 cols

__global__ void fused_l1_kernel(const float* __restrict__ x,
                                const float* __restrict__ w1,
                                const float* __restrict__ b1) {
    __shared__ float ring[L1_D][L1_TILE];

    const int chunk = blockIdx.x;          // 0..11 (16-wide col chunks)
    const int oh    = blockIdx.y;          // 0..49
    const int ow0   = chunk * 16;
    const int tid   = threadIdx.x;         // 64 threads
    const int oc    = tid & 3;
    const int j     = tid >> 2;            // 0..15 (local output col)
    const int ow    = ow0 + j;
    const bool act  = (ow < W1);
    const int pos   = oh * W1 + ow;

    float wv[9];
    #pragma unroll
    for (int i = 0; i < 9; i++) wv[i] = __ldg(&w1[oc * 9 + i]);
    const float bias = __ldg(&b1[oc]);

    const int gr0 = 2 * oh, gc0 = 2 * ow0;

    // Hoisted per-thread load descriptors (each thread fills <=2 tile slots)
    const unsigned ring_base =
        (unsigned)__cvta_generic_to_shared(&ring[0][0]);
    const int i0 = tid;
    const int r_0 = i0 / 33, cc_0 = i0 - r_0 * 33;
    const bool v_0 = (i0 < L1_TILE) && (gr0 + r_0 < H0) && (gc0 + cc_0 < W0);
    const int go_0 = v_0 ? (gr0 + r_0) * W0 + (gc0 + cc_0) : 0;
    const int sz_0 = v_0 ? 4 : 0;
    const int i1 = tid + 64;
    const bool has1 = (i1 < L1_TILE);
    const int r_1 = i1 / 33, cc_1 = i1 - r_1 * 33;
    const bool v_1 = has1 && (gr0 + r_1 < H0) && (gc0 + cc_1 < W0);
    const int go_1 = v_1 ? (gr0 + r_1) * W0 + (gc0 + cc_1) : 0;
    const int sz_1 = v_1 ? 4 : 0;

    auto issue = [&](int slot, int t) {
        const float* xt = x + (size_t)t * P0;
        unsigned d0 = ring_base + (unsigned)(slot * L1_TILE + i0) * 4u;
        asm volatile("cp.async.ca.shared.global [%0], [%1], 4, %2;"
                     :: "r"(d0), "l"(xt + go_0), "r"(sz_0));
        if (has1) {
            unsigned d1 = ring_base + (unsigned)(slot * L1_TILE + i1) * 4u;
            asm volatile("cp.async.ca.shared.global [%0], [%1], 4, %2;"
                         :: "r"(d1), "l"(xt + go_1), "r"(sz_1));
        }
        asm volatile("cp.async.commit_group;" ::: "memory");
    };

    // Prologue: tiles 0..D-2
    for (int d = 0; d < L1_D - 1; d++) issue(d, d);

    float m = 0.0f;
    int t = 0;
    for (int k = 0; k < KBINS; k++) {
        float sum = 0.0f, sq = 0.0f;
        for (int s = 0; s < SBIN; s++, t++) {
            asm volatile("cp.async.wait_group %0;" :: "n"(L1_D - 2) : "memory");
            __syncthreads();

            const float* xs = ring[t % L1_D];
            float cur = bias;
            #pragma unroll
            for (int kh = 0; kh < 3; kh++)
                #pragma unroll
                for (int kw = 0; kw < 3; kw++)
                    cur = __fmaf_rn(xs[kh * 33 + 2 * j + kw],
                                    wv[kh * 3 + kw], cur);

            // exact mul-then-add mirrors BETA*m + conv
            m = __fadd_rn(__fmul_rn(0.9f, m), cur);
            float u = __fadd_rn(m, -1.0f);
            bool spk = (u > 0.0f);
            if (act)
                g_s1[(size_t)t * N1 + pos * 4 + oc] =
                    spk ? (unsigned char)1 : (unsigned char)0;
            m = spk ? u : m;                 // soft reset (exact)
            sum = __fadd_rn(sum, m);
            sq  = __fmaf_rn(m, m, sq);

            int tt = t + L1_D - 1;
            if (tt < T_STEPS) issue(tt % L1_D, tt);
            else asm volatile("cp.async.commit_group;" ::: "memory");
        }
        if (act) {
            float mu  = __fdiv_rn(sum, (float)SBIN);
            float var = __fsub_rn(__fdiv_rn(sq, (float)SBIN), __fmul_rn(mu, mu));
            float sd  = __fsqrt_rn(fmaxf(var, 1e-8f));
            g_skip1[(size_t)(k * 8 + oc) * P1 + pos]     = mu;
            g_skip1[(size_t)(k * 8 + 4 + oc) * P1 + pos] = sd;
        }
    }
}

// ---------------------------------------------------------------------------
// Spike conv (stride 2, SAME), channel-last in AND out. 2D grid: blockIdx.y
// carries t (kills the idx/P division that showed as ALU-pipe load).
// All 9 tap words preloaded into registers (independent LDGs, zero-filled
// invalid taps) before accumulation; accumulation order unchanged.
// ---------------------------------------------------------------------------
template<int CIN, int COUT>
__device__ __forceinline__ void tap_accum_word(unsigned int v, const float* ws,
                                               int ic_base, int tap,
                                               float (&acc)[COUT]) {
    #pragma unroll
    for (int j = 0; j < 4 && ic_base + j < CIN; j++) {
        if ((v >> (8 * j)) & 0xffu) {
            const float* wv = &ws[((ic_base + j) * 9 + tap) * COUT];
            #pragma unroll
            for (int o = 0; o < COUT; o++)
                acc[o] = __fadd_rn(acc[o], wv[o]);
        }
    }
}

template<int L, int CIN, int COUT, int IH, int IW, int OH, int OW, int PH>
__global__ void convs_kernel(const float* __restrict__ w,
                             const float* __restrict__ b) {
    constexpr int P  = OH * OW;
    constexpr int NI = CIN * IH * IW;
    constexpr int NW = CIN * 9 * COUT;
    const unsigned char* __restrict__ spk = sbuf_of<L - 1>();
    float* __restrict__ cbuf = cbuf_of<L>();

    __shared__ __align__(16) float ws[NW];
    __shared__ float bs[COUT];
    for (int i = threadIdx.x; i < NW; i += blockDim.x) {
        int oc = i / (CIN * 9);
        int j  = i - oc * (CIN * 9);        // ic*9 + tap
        ws[j * COUT + oc] = w[i];
    }
    for (int i = threadIdx.x; i < COUT; i += blockDim.x) bs[i] = b[i];
    __syncthreads();

    const int t = blockIdx.y;
    const int pos = blockIdx.x * blockDim.x + threadIdx.x;
    if (pos >= P) return;
    int oh = pos / OW, ow = pos - oh * OW;

    float acc[COUT];
    #pragma unroll
    for (int o = 0; o < COUT; o++) acc[o] = bs[o];

    const unsigned char* sp = spk + (size_t)t * NI;

    if constexpr (CIN == 4) {
        unsigned int v[9];
        #pragma unroll
        for (int kh = 0; kh < 3; kh++)
            #pragma unroll
            for (int kw = 0; kw < 3; kw++) {
                int tap = kh * 3 + kw;
                int r = 2 * oh + kh - PH, cc = 2 * ow + kw;
                bool val = (r >= 0) && (r < IH) && (cc < IW);
                v[tap] = val
                    ? __ldg((const unsigned int*)(sp + (size_t)(r * IW + cc) * CIN))
                    : 0u;
            }
        #pragma unroll
        for (int tap = 0; tap < 9; tap++)
            tap_accum_word<CIN, COUT>(v[tap], ws, 0, tap, acc);
    } else if constexpr (CIN == 8) {
        uint2 v[9];
        #pragma unroll
        for (int kh = 0; kh < 3; kh++)
            #pragma unroll
            for (int kw = 0; kw < 3; kw++) {
                int tap = kh * 3 + kw;
                int r = 2 * oh + kh - PH, cc = 2 * ow + kw;
                bool val = (r >= 0) && (r < IH) && (cc < IW);
                v[tap] = val
                    ? __ldg((const uint2*)(sp + (size_t)(r * IW + cc) * CIN))
                    : make_uint2(0u, 0u);
            }
        #pragma unroll
        for (int tap = 0; tap < 9; tap++) {
            tap_accum_word<CIN, COUT>(v[tap].x, ws, 0, tap, acc);
            tap_accum_word<CIN, COUT>(v[tap].y, ws, 4, tap, acc);
        }
    } else {  // CIN == 16
        uint4 v[9];
        #pragma unroll
        for (int kh = 0; kh < 3; kh++)
            #pragma unroll
            for (int kw = 0; kw < 3; kw++) {
                int tap = kh * 3 + kw;
                int r = 2 * oh + kh - PH, cc = 2 * ow + kw;
                bool val = (r >= 0) && (r < IH) && (cc < IW);
                v[tap] = val
                    ? __ldg((const uint4*)(sp + (size_t)(r * IW + cc) * CIN))
                    : make_uint4(0u, 0u, 0u, 0u);
            }
        #pragma unroll
        for (int tap = 0; tap < 9; tap++) {
            tap_accum_word<CIN, COUT>(v[tap].x, ws, 0,  tap, acc);
            tap_accum_word<CIN, COUT>(v[tap].y, ws, 4,  tap, acc);
            tap_accum_word<CIN, COUT>(v[tap].z, ws, 8,  tap, acc);
            tap_accum_word<CIN, COUT>(v[tap].w, ws, 12, tap, acc);
        }
    }

    float4* out = (float4*)(cbuf + ((size_t)t * P + pos) * COUT);
    #pragma unroll
    for (int o = 0; o < COUT / 4; o++)
        out[o] = make_float4(acc[4 * o], acc[4 * o + 1],
                             acc[4 * o + 2], acc[4 * o + 3]);
}

// ---------------------------------------------------------------------------
// Per-neuron membrane scan (layers 2-4): TWO neurons per thread (i and i+N/2)
// to interleave two independent dependency chains in the issue slots (the
// scans run at ~1 warp/SMSP -- chain-bound, not memory-bound). UF=25 per
// neuron, A/B named register buffers with compile-time selection (no spills).
// Both current streams and spike writes stay fully coalesced.
// ---------------------------------------------------------------------------
#define UF 25

template<int N, bool WRITE_S>
__device__ __forceinline__ void scan_group2(const float* __restrict__ cp0,
                                            const float* __restrict__ cp1,
                                            unsigned char* __restrict__ sb0,
                                            unsigned char* __restrict__ sb1,
                                            int tproc,
                                            float (&p0)[UF], float (&q0)[UF],
                                            float (&p1)[UF], float (&q1)[UF],
                                            float& m0, float& s0, float& z0,
                                            float& m1, float& s1, float& z1) {
    const int tpre = tproc + UF;
    if (tpre < T_STEPS) {
        #pragma unroll
        for (int j = 0; j < UF; j++) {
            q0[j] = __ldg(cp0 + (size_t)(tpre + j) * N);
            q1[j] = __ldg(cp1 + (size_t)(tpre + j) * N);
        }
    }
    #pragma unroll
    for (int j = 0; j < UF; j++) {
        m0 = __fadd_rn(__fmul_rn(0.9f, m0), p0[j]);
        m1 = __fadd_rn(__fmul_rn(0.9f, m1), p1[j]);
        float u0 = __fadd_rn(m0, -1.0f);
        float u1 = __fadd_rn(m1, -1.0f);
        bool k0 = (u0 > 0.0f);
        bool k1 = (u1 > 0.0f);
        if (WRITE_S) {
            sb0[(size_t)(tproc + j) * N] = k0 ? (unsigned char)1 : (unsigned char)0;
            sb1[(size_t)(tproc + j) * N] = k1 ? (unsigned char)1 : (unsigned char)0;
        }
        m0 = k0 ? u0 : m0;
        m1 = k1 ? u1 : m1;
        s0 = __fadd_rn(s0, m0);
        s1 = __fadd_rn(s1, m1);
        z0 = __fmaf_rn(m0, m0, z0);
        z1 = __fmaf_rn(m1, m1, z1);
    }
}

template<int L, int C, int P, bool WRITE_S>
__global__ void scan_kernel() {
    constexpr int N = C * P;
    constexpr int H = N / 2;
    const float* __restrict__ cbuf = cbuf_of<L>();
    float* __restrict__ skip = skip_of<L>();

    int i = blockIdx.x * blockDim.x + threadIdx.x;
    if (i >= H) return;
    // neuron 0: n=i, neuron 1: n=i+H  (n = pos*C + c)
    int pos0 = i / C,       c0 = i - pos0 * C;
    int pos1 = (i + H) / C, c1 = (i + H) - pos1 * C;

    const float* cp0 = cbuf + i;
    const float* cp1 = cbuf + i + H;
    unsigned char* sb0 = (unsigned char*)0;
    unsigned char* sb1 = (unsigned char*)0;
    if (WRITE_S) { sb0 = sbuf_of<L>() + i; sb1 = sbuf_of<L>() + i + H; }

    float A0[UF], B0[UF], A1[UF], B1[UF];
    #pragma unroll
    for (int j = 0; j < UF; j++) {
        A0[j] = __ldg(cp0 + (size_t)j * N);
        A1[j] = __ldg(cp1 + (size_t)j * N);
    }

    float m0 = 0.0f, m1 = 0.0f;
    int t = 0;
    for (int k = 0; k < KBINS; k++) {
        float s0 = 0.0f, z0 = 0.0f, s1 = 0.0f, z1 = 0.0f;
        scan_group2<N, WRITE_S>(cp0, cp1, sb0, sb1, t, A0, B0, A1, B1,
                                m0, s0, z0, m1, s1, z1); t += UF;
        scan_group2<N, WRITE_S>(cp0, cp1, sb0, sb1, t, B0, A0, B1, A1,
                                m0, s0, z0, m1, s1, z1); t += UF;
        scan_group2<N, WRITE_S>(cp0, cp1, sb0, sb1, t, A0, B0, A1, B1,
                                m0, s0, z0, m1, s1, z1); t += UF;
        scan_group2<N, WRITE_S>(cp0, cp1, sb0, sb1, t, B0, A0, B1, A1,
                                m0, s0, z0, m1, s1, z1); t += UF;

        float mu0  = __fdiv_rn(s0, (float)SBIN);
        float var0 = __fsub_rn(__fdiv_rn(z0, (float)SBIN), __fmul_rn(mu0, mu0));
        float sd0  = __fsqrt_rn(fmaxf(var0, 1e-8f));
        skip[(size_t)(k * 2 * C + c0) * P + pos0]     = mu0;
        skip[(size_t)(k * 2 * C + C + c0) * P + pos0] = sd0;

        float mu1  = __fdiv_rn(s1, (float)SBIN);
        float var1 = __fsub_rn(__fdiv_rn(z1, (float)SBIN), __fmul_rn(mu1, mu1));
        float sd1  = __fsqrt_rn(fmaxf(var1, 1e-8f));
        skip[(size_t)(k * 2 * C + c1) * P + pos1]     = mu1;
        skip[(size_t)(k * 2 * C + C + c1) * P + pos1] = sd1;
    }
}

// ---------------------------------------------------------------------------
// Decoder stage 4 (640 -> 64 @ 7x23), ci-split 8 ways.
// ---------------------------------------------------------------------------
__global__ void dconv4_split_kernel(const float* __restrict__ w,
                                    const float* __restrict__ b) {
    __shared__ float ws[640 * 9];       // 23 KB
    __shared__ float red[8][32];
    const int oc = blockIdx.y;
    const int tid = threadIdx.x;
    for (int i = tid; i < 640 * 9; i += 256) ws[i] = __ldg(&w[oc * 640 * 9 + i]);
    __syncthreads();

    const int j = tid & 31, q = tid >> 5;
    const int pos = blockIdx.x * 32 + j;
    const bool act = (pos < P4);
    const int pc = act ? pos : (P4 - 1);
    const int oh = pc / W4, ow = pc - oh * W4;

    bool rv[3], cv[3];
    #pragma unroll
    for (int kh = 0; kh < 3; kh++) { int r = oh + kh - 1; rv[kh] = (r >= 0 && r < H4); }
    #pragma unroll
    for (int kw = 0; kw < 3; kw++) { int cc = ow + kw - 1; cv[kw] = (cc >= 0 && cc < W4); }

    float a = 0.0f;
    const int ci0 = q * 80;
    for (int ci = ci0; ci < ci0 + 80; ci++) {
        const float* src = g_skip4 + (size_t)ci * P4;
        const float* wv = ws + ci * 9;
        #pragma unroll
        for (int kh = 0; kh < 3; kh++) {
            if (!rv[kh]) continue;
            int r = oh + kh - 1;
            #pragma unroll
            for (int kw = 0; kw < 3; kw++) {
                if (!cv[kw]) continue;
                int cc = ow + kw - 1;
                a = __fmaf_rn(__ldg(&src[r * W4 + cc]), wv[kh * 3 + kw], a);
            }
        }
    }
    red[q][j] = a;
    __syncthreads();
    if (q == 0 && act) {
        float tot = __ldg(&b[oc]);
        #pragma unroll
        for (int qq = 0; qq < 8; qq++) tot = __fadd_rn(tot, red[qq][j]);
        tot = fmaxf(tot, 0.0f);
        g_d4[(size_t)oc * P4 + pos] = tot;
    }
}

// ---------------------------------------------------------------------------
// Decoder stages 3/2/1: ci-split 4 ways, weights staged in smem,
// 3 rotating accumulators. Block = 32 pos x 4 ci-groups = 128 threads.
// ---------------------------------------------------------------------------
template<int STAGE, int C1, int C2, int COUT, int HH, int WW>
__global__ void dconv_split_kernel(const float* __restrict__ w,
                                   const float* __restrict__ b) {
    constexpr int P = HH * WW;
    constexpr int CTOT = C1 + C2;
    constexpr int CPG = CTOT / 4;
    const float* in1;
    const float* in2;
    float* outp;
    if constexpr (STAGE == 3) { in1 = g_u4; in2 = g_skip3; outp = g_d3; }
    else if constexpr (STAGE == 2) { in1 = g_u3; in2 = g_skip2; outp = g_d2; }
    else { in1 = g_u2; in2 = g_skip1; outp = g_d1; }

    __shared__ float ws[CTOT * 9];
    __shared__ float red[4][32];
    const int oc = blockIdx.y;
    const int tid = threadIdx.x;
    for (int i = tid; i < CTOT * 9; i += 128) ws[i] = __ldg(&w[oc * CTOT * 9 + i]);
    __syncthreads();

    const int j = tid & 31, q = tid >> 5;
    const int pos = blockIdx.x * 32 + j;
    const bool act = (pos < P);
    const int pc = act ? pos : (P - 1);
    const int oh = pc / WW, ow = pc - oh * WW;

    bool rv[3], cv[3];
    #pragma unroll
    for (int kh = 0; kh < 3; kh++) { int r = oh + kh - 1; rv[kh] = (r >= 0 && r < HH); }
    #pragma unroll
    for (int kw = 0; kw < 3; kw++) { int cc = ow + kw - 1; cv[kw] = (cc >= 0 && cc < WW); }

    float a0 = 0.0f, a1 = 0.0f, a2 = 0.0f;
    const int ci0 = q * CPG;
    #pragma unroll 2
    for (int ci = ci0; ci < ci0 + CPG; ci++) {
        const float* src = (ci < C1) ? (in1 + (size_t)ci * P)
                                     : (in2 + (size_t)(ci - C1) * P);
        const float* wv = ws + ci * 9;
        #pragma unroll
        for (int kh = 0; kh < 3; kh++) {
            if (!rv[kh]) continue;
            int r = oh + kh - 1;
            float aa = (kh == 0) ? a0 : (kh == 1) ? a1 : a2;
            #pragma unroll
            for (int kw = 0; kw < 3; kw++) {
                if (!cv[kw]) continue;
                int cc = ow + kw - 1;
                aa = __fmaf_rn(__ldg(&src[r * WW + cc]), wv[kh * 3 + kw], aa);
            }
            if (kh == 0) a0 = aa; else if (kh == 1) a1 = aa; else a2 = aa;
        }
    }
    red[q][j] = __fadd_rn(__fadd_rn(a0, a1), a2);
    __syncthreads();
    if (q == 0 && act) {
        float tot = __ldg(&b[oc]);
        #pragma unroll
        for (int qq = 0; qq < 4; qq++) tot = __fadd_rn(tot, red[qq][j]);
        tot = fmaxf(tot, 0.0f);
        outp[(size_t)oc * P + pos] = tot;
    }
}

// ---------------------------------------------------------------------------
// Bilinear upsample (half-pixel centers, edge clamp).
// ---------------------------------------------------------------------------
template<int STAGE, int C, int IHH, int IWW, int OHH, int OWW>
__global__ void upsample_kernel() {
    constexpr int OP = OHH * OWW;
    constexpr int IP = IHH * IWW;
    const float* in;
    float* outp;
    if constexpr (STAGE == 4) { in = g_d4; outp = g_u4; }
    else if constexpr (STAGE == 3) { in = g_d3; outp = g_u3; }
    else if constexpr (STAGE == 2) { in = g_d2; outp = g_u2; }
    else { in = g_d1; outp = g_u1; }

    int idx = blockIdx.x * blockDim.x + threadIdx.x;
    if (idx >= C * OP) return;
    int cch = idx / OP;
    int rem = idx - cch * OP;
    int oh = rem / OWW, ow = rem - oh * OWW;

    float sy = (oh + 0.5f) * ((float)IHH / (float)OHH) - 0.5f;
    float sx = (ow + 0.5f) * ((float)IWW / (float)OWW) - 0.5f;
    float fy = floorf(sy), fx = floorf(sx);
    float wy = sy - fy, wx = sx - fx;
    int y0 = (int)fy, x0 = (int)fx;
    int y0c = max(y0, 0), y1c = min(y0 + 1, IHH - 1);
    int x0c = max(x0, 0), x1c = min(x0 + 1, IWW - 1);

    const float* src = in + (size_t)cch * IP;
    float v00 = __ldg(&src[y0c * IWW + x0c]);
    float v01 = __ldg(&src[y0c * IWW + x1c]);
    float v10 = __ldg(&src[y1c * IWW + x0c]);
    float v11 = __ldg(&src[y1c * IWW + x1c]);
    float top = __fadd_rn(__fmul_rn(1.0f - wx, v00), __fmul_rn(wx, v01));
    float bot = __fadd_rn(__fmul_rn(1.0f - wx, v10), __fmul_rn(wx, v11));
    outp[idx] = __fadd_rn(__fmul_rn(1.0f - wy, top), __fmul_rn(wy, bot));
}

// ---------------------------------------------------------------------------
// Final 1x1 conv: g_u1[8,100,368] -> out[1,100,368]
// ---------------------------------------------------------------------------
__global__ void outconv_kernel(const float* __restrict__ wo,
                               const float* __restrict__ bo,
                               float* __restrict__ out) {
    int pos = blockIdx.x * blockDim.x + threadIdx.x;
    if (pos >= P0) return;
    float acc = __ldg(&bo[0]);
    #pragma unroll
    for (int cch = 0; cch < 8; cch++)
        acc = __fmaf_rn(g_u1[cch * P0 + pos], __ldg(&wo[cch]), acc);
    out[pos] = acc;
}

// ---------------------------------------------------------------------------
// Host launcher: kernel launches ONLY.
// ---------------------------------------------------------------------------
static inline int cdiv(int a, int b) { return (a + b - 1) / b; }

extern "C" void kernel_launch(void* const* d_in, const int* in_sizes, int n_in,
                              void* d_out, int out_size) {
    const float* x   = (const float*)d_in[0];
    const float* w1  = (const float*)d_in[1];
    const float* b1  = (const float*)d_in[2];
    const float* w2  = (const float*)d_in[3];
    const float* b2  = (const float*)d_in[4];
    const float* w3  = (const float*)d_in[5];
    const float* b3  = (const float*)d_in[6];
    const float* w4  = (const float*)d_in[7];
    const float* b4  = (const float*)d_in[8];
    const float* dw4 = (const float*)d_in[9];
    const float* db4 = (const float*)d_in[10];
    const float* dw3 = (const float*)d_in[11];
    const float* db3 = (const float*)d_in[12];
    const float* dw2 = (const float*)d_in[13];
    const float* db2 = (const float*)d_in[14];
    const float* dw1 = (const float*)d_in[15];
    const float* db1 = (const float*)d_in[16];
    const float* wo  = (const float*)d_in[17];
    const float* bo  = (const float*)d_in[18];
    float* out = (float*)d_out;

    // ---- Encoder ----
    {   dim3 grid(12, 50);   // fused conv1 + scan1 (64-thread blocks)
        fused_l1_kernel<<<grid, 64>>>(x, w1, b1);
    }

    {   dim3 grid(cdiv(P2, 128), T_STEPS);
        convs_kernel<2, 4, 8, H1, W1, H2, W2, 0><<<grid, 128>>>(w2, b2);
    }
    scan_kernel<2, 8, P2, true><<<cdiv(N2 / 2, 64), 64>>>();

    {   dim3 grid(cdiv(P3, 128), T_STEPS);
        convs_kernel<3, 8, 16, H2, W2, H3, W3, 1><<<grid, 128>>>(w3, b3);
    }
    scan_kernel<3, 16, P3, true><<<cdiv(N3 / 2, 64), 64>>>();

    {   dim3 grid(cdiv(P4, 128), T_STEPS);
        convs_kernel<4, 16, 32, H3, W3, H4, W4, 1><<<grid, 128>>>(w4, b4);
    }
    scan_kernel<4, 32, P4, false><<<cdiv(N4 / 2, 64), 64>>>();

    // ---- Decoder ----
    {   dim3 grid(cdiv(P4, 32), 64);    // dec4: 640 -> 64 @ 7x23 (ci-split x8)
        dconv4_split_kernel<<<grid, 256>>>(dw4, db4);
    }
    upsample_kernel<4, 64, H4, W4, H3, W3><<<cdiv(64 * P3, 256), 256>>>();
    {   dim3 grid(cdiv(P3, 32), 32);    // dec3: 384 -> 32 @ 13x46 (ci-split x4)
        dconv_split_kernel<3, 64, 320, 32, H3, W3><<<grid, 128>>>(dw3, db3);
    }
    upsample_kernel<3, 32, H3, W3, H2, W2><<<cdiv(32 * P2, 256), 256>>>();
    {   dim3 grid(cdiv(P2, 32), 16);    // dec2: 192 -> 16 @ 25x92 (ci-split x4)
        dconv_split_kernel<2, 32, 160, 16, H2, W2><<<grid, 128>>>(dw2, db2);
    }
    upsample_kernel<2, 16, H2, W2, H1, W1><<<cdiv(16 * P1, 256), 256>>>();
    {   dim3 grid(cdiv(P1, 32), 8);     // dec1: 96 -> 8 @ 50x184 (ci-split x4)
        dconv_split_kernel<1, 16, 80, 8, H1, W1><<<grid, 128>>>(dw1, db1);
    }
    upsample_kernel<1, 8, H1, W1, H0, W0><<<cdiv(8 * P0, 256), 256>>>();
    outconv_kernel<<<cdiv(P0, 256), 256>>>(wo, bo, out);
}